// round 6
// baseline (speedup 1.0000x reference)
#include <cuda_runtime.h>
#include <math.h>

#define NN 4096
#define DIN 512
#define DQ 128
#define NG 16
#define NPG 256

// device scratch (no allocations allowed)
__device__ float g_q[NN * DQ];    // [node][dim]  (A operand of QK^T)
__device__ float g_k[NN * DQ];    // [node][dim]  (B operand of QK^T: [n][k])
__device__ float g_vT[DQ * NN];   // [dim][node]  (B operand of P@V:  [n][k])

__device__ __forceinline__ unsigned f2tf(float f) {
    unsigned u;
    asm("cvt.rna.tf32.f32 %0, %1;" : "=r"(u) : "f"(f));
    return u;
}

__device__ __forceinline__ void mma_tf32(float& d0, float& d1, float& d2, float& d3,
                                         unsigned a0, unsigned a1, unsigned a2, unsigned a3,
                                         unsigned b0, unsigned b1) {
    asm volatile(
        "mma.sync.aligned.m16n8k8.row.col.f32.tf32.tf32.f32 "
        "{%0,%1,%2,%3},{%4,%5,%6,%7},{%8,%9},{%0,%1,%2,%3};"
        : "+f"(d0), "+f"(d1), "+f"(d2), "+f"(d3)
        : "r"(a0), "r"(a1), "r"(a2), "r"(a3), "r"(b0), "r"(b1));
}

// ---------------------------------------------------------------------------
// Kernel 1: projections via tf32 mma with register double-buffered k-chunks.
// C[4096,128] = X[4096,512] @ W[128,512]^T. CTA: 64 M x 128 N, 8 warps
// (2Mx4N, warp m32xn32). grid = (64 m-tiles, 3). z: 0->g_q, 1->g_k, 2->g_vT.
// ---------------------------------------------------------------------------
__global__ void __launch_bounds__(256)
proj_kernel(const float* __restrict__ x,
            const float* __restrict__ Wq, const float* __restrict__ bq,
            const float* __restrict__ Wk, const float* __restrict__ bk,
            const float* __restrict__ Wv, const float* __restrict__ bv)
{
    const int z = blockIdx.y;
    const float* W    = (z == 0) ? Wq : (z == 1) ? Wk : Wv;
    const float* bias = (z == 0) ? bq : (z == 1) ? bk : bv;

    __shared__ float Xs[64][36];
    __shared__ float Ws[128][36];

    const int tid  = threadIdx.x;
    const int w    = tid >> 5;
    const int lane = tid & 31;
    const int gid  = lane >> 2;
    const int tig  = lane & 3;
    const int wm   = w >> 2;
    const int wn   = w & 3;
    const int rowBase = blockIdx.x * 64;

    const int lr = tid >> 3;        // 0..31
    const int lc = (tid & 7) * 4;   // 0..28

    float acc[2][4][4];
    #pragma unroll
    for (int i = 0; i < 2; i++)
        #pragma unroll
        for (int j = 0; j < 4; j++)
            #pragma unroll
            for (int t = 0; t < 4; t++) acc[i][j][t] = 0.f;

    // load chunk 0 directly
    #pragma unroll
    for (int i = 0; i < 2; i++) {
        float4 v = *(const float4*)&x[(size_t)(rowBase + lr + 32 * i) * DIN + lc];
        *(uint4*)&Xs[lr + 32 * i][lc] = make_uint4(f2tf(v.x), f2tf(v.y), f2tf(v.z), f2tf(v.w));
    }
    #pragma unroll
    for (int i = 0; i < 4; i++) {
        float4 v = *(const float4*)&W[(size_t)(lr + 32 * i) * DIN + lc];
        *(uint4*)&Ws[lr + 32 * i][lc] = make_uint4(f2tf(v.x), f2tf(v.y), f2tf(v.z), f2tf(v.w));
    }
    __syncthreads();

    for (int kc = 0; kc < 16; kc++) {
        float4 xpre[2], wpre[4];
        if (kc < 15) {
            const int kN = (kc + 1) * 32;
            #pragma unroll
            for (int i = 0; i < 2; i++)
                xpre[i] = *(const float4*)&x[(size_t)(rowBase + lr + 32 * i) * DIN + kN + lc];
            #pragma unroll
            for (int i = 0; i < 4; i++)
                wpre[i] = *(const float4*)&W[(size_t)(lr + 32 * i) * DIN + kN + lc];
        }

        #pragma unroll
        for (int ks = 0; ks < 4; ks++) {
            const int k0 = ks * 8;
            unsigned a[2][4], b[4][2];
            #pragma unroll
            for (int i = 0; i < 2; i++) {
                const int r = wm * 32 + i * 16 + gid;
                a[i][0] = __float_as_uint(Xs[r][k0 + tig]);
                a[i][1] = __float_as_uint(Xs[r + 8][k0 + tig]);
                a[i][2] = __float_as_uint(Xs[r][k0 + tig + 4]);
                a[i][3] = __float_as_uint(Xs[r + 8][k0 + tig + 4]);
            }
            #pragma unroll
            for (int j = 0; j < 4; j++) {
                const int cN = wn * 32 + j * 8 + gid;
                b[j][0] = __float_as_uint(Ws[cN][k0 + tig]);
                b[j][1] = __float_as_uint(Ws[cN][k0 + tig + 4]);
            }
            #pragma unroll
            for (int i = 0; i < 2; i++)
                #pragma unroll
                for (int j = 0; j < 4; j++)
                    mma_tf32(acc[i][j][0], acc[i][j][1], acc[i][j][2], acc[i][j][3],
                             a[i][0], a[i][1], a[i][2], a[i][3], b[j][0], b[j][1]);
        }
        __syncthreads();
        if (kc < 15) {
            #pragma unroll
            for (int i = 0; i < 2; i++)
                *(uint4*)&Xs[lr + 32 * i][lc] =
                    make_uint4(f2tf(xpre[i].x), f2tf(xpre[i].y), f2tf(xpre[i].z), f2tf(xpre[i].w));
            #pragma unroll
            for (int i = 0; i < 4; i++)
                *(uint4*)&Ws[lr + 32 * i][lc] =
                    make_uint4(f2tf(wpre[i].x), f2tf(wpre[i].y), f2tf(wpre[i].z), f2tf(wpre[i].w));
            __syncthreads();
        }
    }

    #pragma unroll
    for (int i = 0; i < 2; i++) {
        const int r0 = rowBase + wm * 32 + i * 16 + gid;
        #pragma unroll
        for (int j = 0; j < 4; j++) {
            const int c0 = wn * 32 + j * 8 + tig * 2;
            const float bb0 = bias[c0], bb1 = bias[c0 + 1];
            const float v00 = acc[i][j][0] + bb0, v01 = acc[i][j][1] + bb1;
            const float v10 = acc[i][j][2] + bb0, v11 = acc[i][j][3] + bb1;
            if (z == 0) {
                *(float2*)&g_q[(size_t)r0 * DQ + c0]       = make_float2(v00, v01);
                *(float2*)&g_q[(size_t)(r0 + 8) * DQ + c0] = make_float2(v10, v11);
            } else if (z == 1) {
                *(float2*)&g_k[(size_t)r0 * DQ + c0]       = make_float2(v00, v01);
                *(float2*)&g_k[(size_t)(r0 + 8) * DQ + c0] = make_float2(v10, v11);
            } else {
                g_vT[(size_t)c0 * NN + r0]           = v00;
                g_vT[(size_t)(c0 + 1) * NN + r0]     = v01;
                g_vT[(size_t)c0 * NN + r0 + 8]       = v10;
                g_vT[(size_t)(c0 + 1) * NN + r0 + 8] = v11;
            }
        }
    }
}

// ---------------------------------------------------------------------------
// Kernel 2: block-diagonal attention. CTA: 32 rows x 256 cols of one graph,
// 512 threads (16 warps), grid (8 chunks, 16 graphs) = 128 CTAs = one wave.
// b/c/mask prefetched to registers at entry; K/V chunks register
// double-buffered under the MMA loops.
// ---------------------------------------------------------------------------
__global__ void __launch_bounds__(512)
attn_kernel(const float* __restrict__ bmat, const float* __restrict__ cmat,
            const int* __restrict__ mask, float* __restrict__ out)
{
    extern __shared__ float smem[];
    float* Qs = smem;                 // [32][132]  tf32 q
    float* Ps = Qs + 32 * 132;        // [32][260]  logits fp32 -> P tf32
    float* Ks = Ps + 32 * 260;        // [256][36]  K chunk / [128][36] V chunk

    const int g  = blockIdx.y;
    const int bx = blockIdx.x;
    const int rowBase = g * NPG + bx * 32;
    const int gBase   = g * NPG;

    const int tid  = threadIdx.x;
    const int w    = tid >> 5;        // 0..15
    const int lane = tid & 31;
    const int gid  = lane >> 2;
    const int tig  = lane & 3;
    const int wm   = w >> 3;          // 0..1
    const int wn   = w & 7;           // 0..7

    // ---- prefetch b, c, mask for this warp's softmax rows (2w, 2w+1) ----
    float bb[16], cc[16];
    int   mm[16];
    #pragma unroll
    for (int p = 0; p < 2; p++) {
        const size_t base = (size_t)(rowBase + 2 * w + p) * NN + gBase;
        #pragma unroll
        for (int s = 0; s < 8; s++) {
            const int j = lane + 32 * s;
            bb[p * 8 + s] = __ldg(&bmat[base + j]);
            cc[p * 8 + s] = __ldg(&cmat[base + j]);
            mm[p * 8 + s] = __ldg(&mask[base + j]);
        }
    }
    float bc[16];
    unsigned kpb[2] = {0u, 0u};
    #pragma unroll
    for (int p = 0; p < 2; p++)
        #pragma unroll
        for (int s = 0; s < 8; s++) {
            bc[p * 8 + s] = bb[p * 8 + s] + cc[p * 8 + s];
            kpb[p] |= (mm[p * 8 + s] != 0 ? 1u : 0u) << s;
        }

    // ---- load Q (32 x 128) as tf32 ----
    {
        const int r = tid >> 4;           // 0..31
        const int c = (tid & 15) * 8;     // 0..120
        #pragma unroll
        for (int h = 0; h < 2; h++) {
            float4 v = *(const float4*)&g_q[(size_t)(rowBase + r) * DQ + c + 4 * h];
            *(uint4*)&Qs[r * 132 + c + 4 * h] =
                make_uint4(f2tf(v.x), f2tf(v.y), f2tf(v.z), f2tf(v.w));
        }
    }

    // ---- load K chunk 0 ----
    {
        const int node = tid >> 1;            // 0..255
        const int d0   = (tid & 1) * 16;      // 0 or 16
        #pragma unroll
        for (int i = 0; i < 4; i++) {
            float4 v = *(const float4*)&g_k[(size_t)(gBase + node) * DQ + d0 + 4 * i];
            *(uint4*)&Ks[node * 36 + d0 + 4 * i] =
                make_uint4(f2tf(v.x), f2tf(v.y), f2tf(v.z), f2tf(v.w));
        }
    }
    __syncthreads();

    // ---- Phase 1: P[32][256] = Q @ K^T. warp (wm,wn): rows wm*16, cols wn*32 ----
    float accp[4][4];
    #pragma unroll
    for (int j = 0; j < 4; j++)
        #pragma unroll
        for (int t = 0; t < 4; t++) accp[j][t] = 0.f;

    for (int kc = 0; kc < 4; kc++) {
        float4 pre[4];
        if (kc < 3) {
            const int node = tid >> 1;
            const int d0   = (tid & 1) * 16;
            #pragma unroll
            for (int i = 0; i < 4; i++)
                pre[i] = *(const float4*)&g_k[(size_t)(gBase + node) * DQ +
                                              (kc + 1) * 32 + d0 + 4 * i];
        }

        #pragma unroll
        for (int ks = 0; ks < 4; ks++) {
            const int k0 = kc * 32 + ks * 8;
            unsigned a0 = __float_as_uint(Qs[(wm * 16 + gid) * 132 + k0 + tig]);
            unsigned a1 = __float_as_uint(Qs[(wm * 16 + 8 + gid) * 132 + k0 + tig]);
            unsigned a2 = __float_as_uint(Qs[(wm * 16 + gid) * 132 + k0 + tig + 4]);
            unsigned a3 = __float_as_uint(Qs[(wm * 16 + 8 + gid) * 132 + k0 + tig + 4]);
            #pragma unroll
            for (int j = 0; j < 4; j++) {
                const int n = wn * 32 + j * 8 + gid;
                unsigned b0 = __float_as_uint(Ks[n * 36 + ks * 8 + tig]);
                unsigned b1 = __float_as_uint(Ks[n * 36 + ks * 8 + tig + 4]);
                mma_tf32(accp[j][0], accp[j][1], accp[j][2], accp[j][3],
                         a0, a1, a2, a3, b0, b1);
            }
        }
        __syncthreads();
        if (kc < 3) {
            const int node = tid >> 1;
            const int d0   = (tid & 1) * 16;
            #pragma unroll
            for (int i = 0; i < 4; i++)
                *(uint4*)&Ks[node * 36 + d0 + 4 * i] =
                    make_uint4(f2tf(pre[i].x), f2tf(pre[i].y), f2tf(pre[i].z), f2tf(pre[i].w));
            __syncthreads();
        }
    }

    // store raw logits (fp32) into Ps
    #pragma unroll
    for (int j = 0; j < 4; j++) {
        const int c0 = wn * 32 + j * 8 + tig * 2;
        *(float2*)&Ps[(wm * 16 + gid) * 260 + c0]     = make_float2(accp[j][0], accp[j][1]);
        *(float2*)&Ps[(wm * 16 + 8 + gid) * 260 + c0] = make_float2(accp[j][2], accp[j][3]);
    }
    __syncthreads();

    // ---- Phase 2: masked softmax, warp w -> rows 2w, 2w+1 (all operands in regs) ----
    const float inv_scale = 0.08838834764831845f;  // 1/sqrt(128)
    #pragma unroll
    for (int p = 0; p < 2; p++) {
        const int r = 2 * w + p;

        float l[8];
        float mx = -1e30f;
        #pragma unroll
        for (int s = 0; s < 8; s++) {
            l[s] = Ps[r * 260 + lane + 32 * s] * inv_scale + bc[p * 8 + s];
            if ((kpb[p] >> s) & 1u) mx = fmaxf(mx, l[s]);
        }
        #pragma unroll
        for (int o = 16; o > 0; o >>= 1)
            mx = fmaxf(mx, __shfl_xor_sync(0xffffffffu, mx, o));

        float e[8];
        float sum = 0.f;
        #pragma unroll
        for (int s = 0; s < 8; s++) {
            e[s] = ((kpb[p] >> s) & 1u) ? __expf(l[s] - mx) : 0.f;
            sum += e[s];
        }
        #pragma unroll
        for (int o = 16; o > 0; o >>= 1)
            sum += __shfl_xor_sync(0xffffffffu, sum, o);

        const float inv = (sum > 0.f) ? (1.f / sum) : 0.f;
        #pragma unroll
        for (int s = 0; s < 8; s++)
            Ps[r * 260 + lane + 32 * s] = __uint_as_float(f2tf(e[s] * inv));
    }
    __syncthreads();

    // ---- Phase 3: out[32][128] = P @ V. warp (wm,wn): rows wm*16, cols wn*16 ----
    float acco[2][4];
    #pragma unroll
    for (int j = 0; j < 2; j++)
        #pragma unroll
        for (int t = 0; t < 4; t++) acco[j][t] = 0.f;

    float* Vs = Ks;   // reuse: [128][36]
    // load V chunk 0
    {
        const int dim = tid >> 2;           // 0..127
        const int nn  = (tid & 3) * 8;      // 0..24
        #pragma unroll
        for (int i = 0; i < 2; i++) {
            float4 v = *(const float4*)&g_vT[(size_t)dim * NN + gBase + nn + 4 * i];
            *(uint4*)&Vs[dim * 36 + nn + 4 * i] =
                make_uint4(f2tf(v.x), f2tf(v.y), f2tf(v.z), f2tf(v.w));
        }
    }
    __syncthreads();

    for (int kc = 0; kc < 8; kc++) {
        float4 pre[2];
        if (kc < 7) {
            const int dim = tid >> 2;
            const int nn  = (tid & 3) * 8;
            #pragma unroll
            for (int i = 0; i < 2; i++)
                pre[i] = *(const float4*)&g_vT[(size_t)dim * NN + gBase +
                                               (kc + 1) * 32 + nn + 4 * i];
        }

        #pragma unroll
        for (int ks = 0; ks < 4; ks++) {
            const int kk = kc * 32 + ks * 8;
            unsigned a0 = __float_as_uint(Ps[(wm * 16 + gid) * 260 + kk + tig]);
            unsigned a1 = __float_as_uint(Ps[(wm * 16 + 8 + gid) * 260 + kk + tig]);
            unsigned a2 = __float_as_uint(Ps[(wm * 16 + gid) * 260 + kk + tig + 4]);
            unsigned a3 = __float_as_uint(Ps[(wm * 16 + 8 + gid) * 260 + kk + tig + 4]);
            #pragma unroll
            for (int j = 0; j < 2; j++) {
                const int n = wn * 16 + j * 8 + gid;   // output dim
                unsigned b0 = __float_as_uint(Vs[n * 36 + ks * 8 + tig]);
                unsigned b1 = __float_as_uint(Vs[n * 36 + ks * 8 + tig + 4]);
                mma_tf32(acco[j][0], acco[j][1], acco[j][2], acco[j][3],
                         a0, a1, a2, a3, b0, b1);
            }
        }
        __syncthreads();
        if (kc < 7) {
            const int dim = tid >> 2;
            const int nn  = (tid & 3) * 8;
            #pragma unroll
            for (int i = 0; i < 2; i++)
                *(uint4*)&Vs[dim * 36 + nn + 4 * i] =
                    make_uint4(f2tf(pre[i].x), f2tf(pre[i].y), f2tf(pre[i].z), f2tf(pre[i].w));
            __syncthreads();
        }
    }

    // epilogue
    #pragma unroll
    for (int j = 0; j < 2; j++) {
        const int c0 = wn * 16 + j * 8 + tig * 2;
        const int r0 = rowBase + wm * 16 + gid;
        *(float2*)&out[(size_t)r0 * DQ + c0]       = make_float2(acco[j][0], acco[j][1]);
        *(float2*)&out[(size_t)(r0 + 8) * DQ + c0] = make_float2(acco[j][2], acco[j][3]);
    }
}

// ---------------------------------------------------------------------------
extern "C" void kernel_launch(void* const* d_in, const int* in_sizes, int n_in,
                              void* d_out, int out_size)
{
    const float* x    = (const float*)d_in[0];
    const float* bmat = (const float*)d_in[1];
    const float* cmat = (const float*)d_in[2];
    // d_in[3] = ptr (int32, 17) — fixed shapes: graph id = node / 256
    const int*   mask = (const int*)d_in[4];
    const float* Wq   = (const float*)d_in[5];
    const float* bq   = (const float*)d_in[6];
    const float* Wk   = (const float*)d_in[7];
    const float* bk   = (const float*)d_in[8];
    const float* Wv   = (const float*)d_in[9];
    const float* bv   = (const float*)d_in[10];
    float* out = (float*)d_out;

    dim3 g1(64, 3);
    proj_kernel<<<g1, 256>>>(x, Wq, bq, Wk, bk, Wv, bv);

    const size_t smem_bytes = (size_t)(32 * 132 + 32 * 260 + 256 * 36) * sizeof(float);
    cudaFuncSetAttribute(attn_kernel,
                         cudaFuncAttributeMaxDynamicSharedMemorySize,
                         (int)smem_bytes);
    dim3 g2(8, 16);
    attn_kernel<<<g2, 512, smem_bytes>>>(bmat, cmat, mask, out);
}

// round 7
// speedup vs baseline: 1.0491x; 1.0491x over previous
#include <cuda_runtime.h>
#include <math.h>
#include <stdint.h>

#define NN 4096
#define DIN 512
#define DQ 128
#define NG 16
#define NPG 256

// device scratch (values pre-rounded to tf32 at proj epilogue)
__device__ float g_q[NN * DQ];    // [node][dim]
__device__ float g_k[NN * DQ];    // [node][dim]
__device__ float g_vT[DQ * NN];   // [dim][node]

__device__ __forceinline__ unsigned f2tf(float f) {
    unsigned u;
    asm("cvt.rna.tf32.f32 %0, %1;" : "=r"(u) : "f"(f));
    return u;
}
__device__ __forceinline__ float f2tff(float f) { return __uint_as_float(f2tf(f)); }

__device__ __forceinline__ void mma_tf32(float& d0, float& d1, float& d2, float& d3,
                                         unsigned a0, unsigned a1, unsigned a2, unsigned a3,
                                         unsigned b0, unsigned b1) {
    asm volatile(
        "mma.sync.aligned.m16n8k8.row.col.f32.tf32.tf32.f32 "
        "{%0,%1,%2,%3},{%4,%5,%6,%7},{%8,%9},{%0,%1,%2,%3};"
        : "+f"(d0), "+f"(d1), "+f"(d2), "+f"(d3)
        : "r"(a0), "r"(a1), "r"(a2), "r"(a3), "r"(b0), "r"(b1));
}

__device__ __forceinline__ void cpa16(uint32_t s, const float* g) {
    asm volatile("cp.async.cg.shared.global [%0], [%1], 16;" :: "r"(s), "l"(g));
}
__device__ __forceinline__ void cpa_commit() {
    asm volatile("cp.async.commit_group;" ::: "memory");
}
template <int N> __device__ __forceinline__ void cpa_wait() {
    asm volatile("cp.async.wait_group %0;" :: "n"(N) : "memory");
}

// ---------------------------------------------------------------------------
// Kernel 1: projections. C[4096,128] = X @ W^T + bias, outputs tf32-rounded.
// 256 threads, CTA tile 64Mx128N, warp m32xn32 (2x4). cp.async double-buffered
// 32-k chunks of raw fp32; cvt.rna on the fragment path. grid (64, 3).
// ---------------------------------------------------------------------------
__global__ void __launch_bounds__(256)
proj_kernel(const float* __restrict__ x,
            const float* __restrict__ Wq, const float* __restrict__ bq,
            const float* __restrict__ Wk, const float* __restrict__ bk,
            const float* __restrict__ Wv, const float* __restrict__ bv)
{
    extern __shared__ float sm[];
    float* Xs = sm;                      // [2][64][36] raw fp32
    float* Ws = sm + 2 * 64 * 36;        // [2][128][36]

    const int z = blockIdx.y;
    const float* W    = (z == 0) ? Wq : (z == 1) ? Wk : Wv;
    const float* bias = (z == 0) ? bq : (z == 1) ? bk : bv;

    const int tid  = threadIdx.x;
    const int w    = tid >> 5;
    const int lane = tid & 31;
    const int gid  = lane >> 2;
    const int tig  = lane & 3;
    const int wm   = w >> 2;
    const int wn   = w & 3;
    const int rowBase = blockIdx.x * 64;

    const uint32_t sb   = (uint32_t)__cvta_generic_to_shared(sm);
    const uint32_t xs_b = sb;
    const uint32_t ws_b = sb + 2 * 64 * 36 * 4;

    const int srow = tid >> 3;           // staging row 0..31
    const int sseg = tid & 7;            // 16B segment 0..7

    float acc[2][4][4];
    #pragma unroll
    for (int i = 0; i < 2; i++)
        #pragma unroll
        for (int j = 0; j < 4; j++)
            #pragma unroll
            for (int t = 0; t < 4; t++) acc[i][j][t] = 0.f;

    // stage chunk 0
    {
        #pragma unroll
        for (int u = 0; u < 2; u++)
            cpa16(xs_b + (uint32_t)((srow + 32 * u) * 36) * 4 + sseg * 16,
                  &x[(size_t)(rowBase + srow + 32 * u) * DIN + sseg * 4]);
        #pragma unroll
        for (int u = 0; u < 4; u++)
            cpa16(ws_b + (uint32_t)((srow + 32 * u) * 36) * 4 + sseg * 16,
                  &W[(size_t)(srow + 32 * u) * DIN + sseg * 4]);
        cpa_commit();
    }

    for (int kc = 0; kc < 16; kc++) {
        if (kc < 15) {
            const int buf = (kc + 1) & 1;
            const int kN = (kc + 1) * 32;
            #pragma unroll
            for (int u = 0; u < 2; u++)
                cpa16(xs_b + (uint32_t)((buf * 64 + srow + 32 * u) * 36) * 4 + sseg * 16,
                      &x[(size_t)(rowBase + srow + 32 * u) * DIN + kN + sseg * 4]);
            #pragma unroll
            for (int u = 0; u < 4; u++)
                cpa16(ws_b + (uint32_t)((buf * 128 + srow + 32 * u) * 36) * 4 + sseg * 16,
                      &W[(size_t)(srow + 32 * u) * DIN + kN + sseg * 4]);
            cpa_commit();
            cpa_wait<1>();
        } else {
            cpa_wait<0>();
        }
        __syncthreads();

        const float* Xb = Xs + (kc & 1) * 64 * 36;
        const float* Wb = Ws + (kc & 1) * 128 * 36;

        #pragma unroll
        for (int ks = 0; ks < 4; ks++) {
            const int k0 = ks * 8;
            unsigned a[2][4], b[4][2];
            #pragma unroll
            for (int i = 0; i < 2; i++) {
                const int r = wm * 32 + i * 16 + gid;
                a[i][0] = f2tf(Xb[r * 36 + k0 + tig]);
                a[i][1] = f2tf(Xb[(r + 8) * 36 + k0 + tig]);
                a[i][2] = f2tf(Xb[r * 36 + k0 + tig + 4]);
                a[i][3] = f2tf(Xb[(r + 8) * 36 + k0 + tig + 4]);
            }
            #pragma unroll
            for (int j = 0; j < 4; j++) {
                const int c = wn * 32 + j * 8 + gid;
                b[j][0] = f2tf(Wb[c * 36 + k0 + tig]);
                b[j][1] = f2tf(Wb[c * 36 + k0 + tig + 4]);
            }
            #pragma unroll
            for (int i = 0; i < 2; i++)
                #pragma unroll
                for (int j = 0; j < 4; j++)
                    mma_tf32(acc[i][j][0], acc[i][j][1], acc[i][j][2], acc[i][j][3],
                             a[i][0], a[i][1], a[i][2], a[i][3], b[j][0], b[j][1]);
        }
        __syncthreads();
    }

    // epilogue: round to tf32 so attn can consume raw bits
    #pragma unroll
    for (int i = 0; i < 2; i++) {
        const int r0 = rowBase + wm * 32 + i * 16 + gid;
        #pragma unroll
        for (int j = 0; j < 4; j++) {
            const int c0 = wn * 32 + j * 8 + tig * 2;
            const float v00 = f2tff(acc[i][j][0] + bias[c0]);
            const float v01 = f2tff(acc[i][j][1] + bias[c0 + 1]);
            const float v10 = f2tff(acc[i][j][2] + bias[c0]);
            const float v11 = f2tff(acc[i][j][3] + bias[c0 + 1]);
            if (z == 0) {
                *(float2*)&g_q[(size_t)r0 * DQ + c0]       = make_float2(v00, v01);
                *(float2*)&g_q[(size_t)(r0 + 8) * DQ + c0] = make_float2(v10, v11);
            } else if (z == 1) {
                *(float2*)&g_k[(size_t)r0 * DQ + c0]       = make_float2(v00, v01);
                *(float2*)&g_k[(size_t)(r0 + 8) * DQ + c0] = make_float2(v10, v11);
            } else {
                g_vT[(size_t)c0 * NN + r0]           = v00;
                g_vT[(size_t)(c0 + 1) * NN + r0]     = v01;
                g_vT[(size_t)c0 * NN + r0 + 8]       = v10;
                g_vT[(size_t)(c0 + 1) * NN + r0 + 8] = v11;
            }
        }
    }
}

// ---------------------------------------------------------------------------
// Kernel 2: block-diagonal attention. 1024 threads (32 warps), grid (8,16)
// = 128 CTAs = one wave. Triple-buffered cp.async staging of K (4x32-node
// chunks) and V (4x64-node chunks, aliased buffers); b/c/mask in registers.
// ---------------------------------------------------------------------------
__global__ void __launch_bounds__(1024)
attn_kernel(const float* __restrict__ bmat, const float* __restrict__ cmat,
            const int* __restrict__ mask, float* __restrict__ out)
{
    extern __shared__ float smem[];
    float* Qs = smem;                   // [32][132]
    float* Ps = Qs + 32 * 132;          // [32][260]
    float* Kb = Ps + 32 * 260;          // [3][256][36]; V aliases [3][128][68]

    const int g  = blockIdx.y;
    const int bx = blockIdx.x;
    const int rowBase = g * NPG + bx * 32;
    const int gBase   = g * NPG;

    const int tid  = threadIdx.x;
    const int w    = tid >> 5;        // 0..31
    const int lane = tid & 31;
    const int gid  = lane >> 2;
    const int tig  = lane & 3;
    const int wm   = w >> 4;          // 0..1
    const int wn   = w & 15;          // 0..15

    const uint32_t sb   = (uint32_t)__cvta_generic_to_shared(smem);
    const uint32_t q_b  = sb;
    const uint32_t kb_b = sb + (32 * 132 + 32 * 260) * 4;

    // ---- stage Q (1 op/thread) + K chunk 0 (2 ops/thread) ----
    {
        const int qrow = tid >> 5, qseg = tid & 31;
        cpa16(q_b + (uint32_t)(qrow * 132) * 4 + qseg * 16,
              &g_q[(size_t)(rowBase + qrow) * DQ + qseg * 4]);
        #pragma unroll
        for (int u = 0; u < 2; u++) {
            const int op = tid + 1024 * u;
            const int node = op >> 3, seg = op & 7;
            cpa16(kb_b + (uint32_t)(node * 36) * 4 + seg * 16,
                  &g_k[(size_t)(gBase + node) * DQ + seg * 4]);
        }
        cpa_commit();
    }

    // ---- prefetch b, c, mask for this warp's softmax row (row = w) ----
    float bc[8];
    unsigned kpb = 0u;
    {
        const size_t base = (size_t)(rowBase + w) * NN + gBase;
        float bb[8], cc[8];
        int mm[8];
        #pragma unroll
        for (int s = 0; s < 8; s++) {
            const int j = lane + 32 * s;
            bb[s] = __ldg(&bmat[base + j]);
            cc[s] = __ldg(&cmat[base + j]);
            mm[s] = __ldg(&mask[base + j]);
        }
        #pragma unroll
        for (int s = 0; s < 8; s++) {
            bc[s] = bb[s] + cc[s];
            kpb |= (mm[s] != 0 ? 1u : 0u) << s;
        }
    }

    // ---- Phase 1: P[32][256] = Q @ K^T. warp: rows wm*16(+16), cols wn*16 ----
    float accp[2][4];
    #pragma unroll
    for (int j = 0; j < 2; j++)
        #pragma unroll
        for (int t = 0; t < 4; t++) accp[j][t] = 0.f;

    #pragma unroll 1
    for (int kc = 0; kc < 4; kc++) {
        if (kc < 3) {
            const uint32_t buf = kb_b + (uint32_t)(((kc + 1) % 3) * 9216) * 4;
            #pragma unroll
            for (int u = 0; u < 2; u++) {
                const int op = tid + 1024 * u;
                const int node = op >> 3, seg = op & 7;
                cpa16(buf + (uint32_t)(node * 36) * 4 + seg * 16,
                      &g_k[(size_t)(gBase + node) * DQ + (kc + 1) * 32 + seg * 4]);
            }
            cpa_commit();
            cpa_wait<1>();
        } else {
            cpa_wait<0>();
        }
        __syncthreads();

        const float* Ks = Kb + (kc % 3) * 9216;
        #pragma unroll
        for (int ks = 0; ks < 4; ks++) {
            const int k0 = kc * 32 + ks * 8;
            unsigned a0 = __float_as_uint(Qs[(wm * 16 + gid) * 132 + k0 + tig]);
            unsigned a1 = __float_as_uint(Qs[(wm * 16 + 8 + gid) * 132 + k0 + tig]);
            unsigned a2 = __float_as_uint(Qs[(wm * 16 + gid) * 132 + k0 + tig + 4]);
            unsigned a3 = __float_as_uint(Qs[(wm * 16 + 8 + gid) * 132 + k0 + tig + 4]);
            #pragma unroll
            for (int j = 0; j < 2; j++) {
                const int n = wn * 16 + j * 8 + gid;
                unsigned b0 = __float_as_uint(Ks[n * 36 + ks * 8 + tig]);
                unsigned b1 = __float_as_uint(Ks[n * 36 + ks * 8 + tig + 4]);
                mma_tf32(accp[j][0], accp[j][1], accp[j][2], accp[j][3],
                         a0, a1, a2, a3, b0, b1);
            }
        }
    }

    // store raw logits (fp32) into Ps
    #pragma unroll
    for (int j = 0; j < 2; j++) {
        const int c0 = wn * 16 + j * 8 + tig * 2;
        *(float2*)&Ps[(wm * 16 + gid) * 260 + c0]     = make_float2(accp[j][0], accp[j][1]);
        *(float2*)&Ps[(wm * 16 + 8 + gid) * 260 + c0] = make_float2(accp[j][2], accp[j][3]);
    }
    __syncthreads();   // all logits visible; all K-buffer reads done

    // ---- stage V chunk 0 (overlaps softmax) ----
    {
        #pragma unroll
        for (int u = 0; u < 2; u++) {
            const int op = tid + 1024 * u;
            const int dim = op >> 4, seg = op & 15;
            cpa16(kb_b + (uint32_t)(dim * 68) * 4 + seg * 16,
                  &g_vT[(size_t)dim * NN + gBase + seg * 4]);
        }
        cpa_commit();
    }

    // ---- Phase 2: masked softmax, warp w -> row w (all operands in regs) ----
    {
        const float inv_scale = 0.08838834764831845f;  // 1/sqrt(128)
        float l[8];
        float mx = -1e30f;
        #pragma unroll
        for (int s = 0; s < 8; s++) {
            l[s] = Ps[w * 260 + lane + 32 * s] * inv_scale + bc[s];
            if ((kpb >> s) & 1u) mx = fmaxf(mx, l[s]);
        }
        #pragma unroll
        for (int o = 16; o > 0; o >>= 1)
            mx = fmaxf(mx, __shfl_xor_sync(0xffffffffu, mx, o));

        float e[8];
        float sum = 0.f;
        #pragma unroll
        for (int s = 0; s < 8; s++) {
            e[s] = ((kpb >> s) & 1u) ? __expf(l[s] - mx) : 0.f;
            sum += e[s];
        }
        #pragma unroll
        for (int o = 16; o > 0; o >>= 1)
            sum += __shfl_xor_sync(0xffffffffu, sum, o);

        const float inv = (sum > 0.f) ? (1.f / sum) : 0.f;
        #pragma unroll
        for (int s = 0; s < 8; s++)
            Ps[w * 260 + lane + 32 * s] = f2tff(e[s] * inv);
    }

    // ---- Phase 3: out[32][128] = P @ V. 4 chunks of 64 nodes.
    //      warp: rows wm*16(+16), cols wn*8 ----
    float acco[4];
    #pragma unroll
    for (int t = 0; t < 4; t++) acco[t] = 0.f;

    #pragma unroll 1
    for (int kc = 0; kc < 4; kc++) {
        if (kc < 3) {
            const uint32_t buf = kb_b + (uint32_t)(((kc + 1) % 3) * 9216) * 4;
            #pragma unroll
            for (int u = 0; u < 2; u++) {
                const int op = tid + 1024 * u;
                const int dim = op >> 4, seg = op & 15;
                cpa16(buf + (uint32_t)(dim * 68) * 4 + seg * 16,
                      &g_vT[(size_t)dim * NN + gBase + (kc + 1) * 64 + seg * 4]);
            }
            cpa_commit();
            cpa_wait<1>();
        } else {
            cpa_wait<0>();
        }
        __syncthreads();   // V chunk ready AND (kc==0) softmax P complete

        const float* Vs = Kb + (kc % 3) * 9216;   // [128][68]
        #pragma unroll
        for (int ks = 0; ks < 8; ks++) {
            const int kk = kc * 64 + ks * 8;
            unsigned a0 = __float_as_uint(Ps[(wm * 16 + gid) * 260 + kk + tig]);
            unsigned a1 = __float_as_uint(Ps[(wm * 16 + 8 + gid) * 260 + kk + tig]);
            unsigned a2 = __float_as_uint(Ps[(wm * 16 + gid) * 260 + kk + tig + 4]);
            unsigned a3 = __float_as_uint(Ps[(wm * 16 + 8 + gid) * 260 + kk + tig + 4]);
            const int n = wn * 8 + gid;
            unsigned b0 = __float_as_uint(Vs[n * 68 + ks * 8 + tig]);
            unsigned b1 = __float_as_uint(Vs[n * 68 + ks * 8 + tig + 4]);
            mma_tf32(acco[0], acco[1], acco[2], acco[3], a0, a1, a2, a3, b0, b1);
        }
    }

    // epilogue
    {
        const int c0 = wn * 8 + tig * 2;
        const int r0 = rowBase + wm * 16 + gid;
        *(float2*)&out[(size_t)r0 * DQ + c0]       = make_float2(acco[0], acco[1]);
        *(float2*)&out[(size_t)(r0 + 8) * DQ + c0] = make_float2(acco[2], acco[3]);
    }
}

// ---------------------------------------------------------------------------
extern "C" void kernel_launch(void* const* d_in, const int* in_sizes, int n_in,
                              void* d_out, int out_size)
{
    const float* x    = (const float*)d_in[0];
    const float* bmat = (const float*)d_in[1];
    const float* cmat = (const float*)d_in[2];
    // d_in[3] = ptr (int32, 17) — fixed shapes: graph id = node / 256
    const int*   mask = (const int*)d_in[4];
    const float* Wq   = (const float*)d_in[5];
    const float* bq   = (const float*)d_in[6];
    const float* Wk   = (const float*)d_in[7];
    const float* bk   = (const float*)d_in[8];
    const float* Wv   = (const float*)d_in[9];
    const float* bv   = (const float*)d_in[10];
    float* out = (float*)d_out;

    const size_t proj_smem = (size_t)(2 * 64 * 36 + 2 * 128 * 36) * sizeof(float);
    cudaFuncSetAttribute(proj_kernel,
                         cudaFuncAttributeMaxDynamicSharedMemorySize, (int)proj_smem);
    dim3 g1(64, 3);
    proj_kernel<<<g1, 256, proj_smem>>>(x, Wq, bq, Wk, bk, Wv, bv);

    const size_t attn_smem = (size_t)(32 * 132 + 32 * 260 + 3 * 256 * 36) * sizeof(float);
    cudaFuncSetAttribute(attn_kernel,
                         cudaFuncAttributeMaxDynamicSharedMemorySize, (int)attn_smem);
    dim3 g2(8, 16);
    attn_kernel<<<g2, 1024, attn_smem>>>(bmat, cmat, mask, out);
}